// round 1
// baseline (speedup 1.0000x reference)
#include <cuda_runtime.h>
#include <cuda_bf16.h>
#include <math.h>

// Problem constants
#define BB 2
#define NN 1024
#define CC 768
#define HH 12
#define DD 64
#define SCALE 0.125f

// ---------------- scratch (device globals; no allocation allowed) ----------------
__device__ float g_qkv[BB * NN * 3 * CC];     // [B,N,3C]
__device__ float g_q[BB * HH * NN * DD];      // [B*H, N, D] normalized q
__device__ float g_k[BB * HH * NN * DD];      // [B*H, N, D] normalized k
__device__ float g_loga[BB * HH * NN];        // [B*H, N] log(a)
__device__ float g_c[BB * HH * (NN + 1)];     // [B*H, N+1] exclusive-prefixed cumsum
__device__ float g_ctx[BB * NN * CC];         // [B,N,C] attention output pre-proj

// ---------------- fast exp (FMA pipe, avoids MUFU) ----------------
// exp(x) for x <= 0 (clamped at underflow). Max rel err ~1.5e-6.
__device__ __forceinline__ float fexp(float x) {
    float t = x * 1.4426950408889634f;   // log2(e)
    t = fmaxf(t, -126.0f);
    float fn = floorf(t);
    float f = t - fn;
    float p = 1.5252734e-5f;
    p = fmaf(p, f, 1.5403530e-4f);
    p = fmaf(p, f, 1.3333558e-3f);
    p = fmaf(p, f, 9.6181291e-3f);
    p = fmaf(p, f, 5.5504109e-2f);
    p = fmaf(p, f, 2.4022651e-1f);
    p = fmaf(p, f, 6.9314718e-1f);
    p = fmaf(p, f, 1.0f);
    int n = (int)fn;
    return p * __int_as_float((n + 127) << 23);
}

// ---------------- SGEMM: C[M,N] = A[M,K] @ W[N,K]^T (+bias) ----------------
// 128x128 block, BK=8, 256 threads, 8x8 micro-tile. All dims divide evenly here.
__global__ __launch_bounds__(256) void sgemm_nt(
    const float* __restrict__ A, const float* __restrict__ W,
    const float* __restrict__ bias, float* __restrict__ C,
    int M, int N, int K)
{
    __shared__ float sA[8][132];
    __shared__ float sB[8][132];
    int tid = threadIdx.x;
    int bm = blockIdx.y * 128;
    int bn = blockIdx.x * 128;
    int tx = tid & 15, ty = tid >> 4;

    float acc[8][8];
#pragma unroll
    for (int i = 0; i < 8; i++)
#pragma unroll
        for (int j = 0; j < 8; j++) acc[i][j] = 0.f;

    int lrow = tid >> 1;            // 0..127
    int lk4  = (tid & 1) * 4;       // 0 or 4
    const float* Aptr = A + (size_t)(bm + lrow) * K + lk4;
    const float* Wptr = W + (size_t)(bn + lrow) * K + lk4;

    for (int k0 = 0; k0 < K; k0 += 8) {
        float4 av = *(const float4*)(Aptr + k0);
        float4 wv = *(const float4*)(Wptr + k0);
        __syncthreads();
        sA[lk4 + 0][lrow] = av.x; sA[lk4 + 1][lrow] = av.y;
        sA[lk4 + 2][lrow] = av.z; sA[lk4 + 3][lrow] = av.w;
        sB[lk4 + 0][lrow] = wv.x; sB[lk4 + 1][lrow] = wv.y;
        sB[lk4 + 2][lrow] = wv.z; sB[lk4 + 3][lrow] = wv.w;
        __syncthreads();
#pragma unroll
        for (int kk = 0; kk < 8; kk++) {
            float4 a0 = *(const float4*)&sA[kk][ty * 8];
            float4 a1 = *(const float4*)&sA[kk][ty * 8 + 4];
            float4 b0 = *(const float4*)&sB[kk][tx * 8];
            float4 b1 = *(const float4*)&sB[kk][tx * 8 + 4];
            float a[8] = {a0.x, a0.y, a0.z, a0.w, a1.x, a1.y, a1.z, a1.w};
            float b[8] = {b0.x, b0.y, b0.z, b0.w, b1.x, b1.y, b1.z, b1.w};
#pragma unroll
            for (int i = 0; i < 8; i++)
#pragma unroll
                for (int j = 0; j < 8; j++)
                    acc[i][j] = fmaf(a[i], b[j], acc[i][j]);
        }
    }

#pragma unroll
    for (int i = 0; i < 8; i++) {
        int row = bm + ty * 8 + i;
#pragma unroll
        for (int j4 = 0; j4 < 2; j4++) {
            int col = bn + tx * 8 + j4 * 4;
            float4 o;
            o.x = acc[i][j4 * 4 + 0];
            o.y = acc[i][j4 * 4 + 1];
            o.z = acc[i][j4 * 4 + 2];
            o.w = acc[i][j4 * 4 + 3];
            if (bias) {
                o.x += bias[col + 0]; o.y += bias[col + 1];
                o.z += bias[col + 2]; o.w += bias[col + 3];
            }
            *(float4*)(C + (size_t)row * N + col) = o;
        }
    }
}

// ---------------- gate logits -> log(a) ----------------
// grid = B*N blocks, 128 threads. loga[b*H+h][n] = log(a), a = 1-sigmoid(x@Wa^T+ba),
// with a forced to 1 at n==0.
__global__ void gate_kernel(const float* __restrict__ x, const float* __restrict__ Wa,
                            const float* __restrict__ ba, float* __restrict__ loga)
{
    int bn = blockIdx.x;                 // 0..2047
    int b = bn >> 10, n = bn & 1023;
    __shared__ float sx[CC];
    __shared__ float warpsum[4];
    int tid = threadIdx.x;
    for (int i = tid; i < CC / 4; i += 128)
        *(float4*)&sx[i * 4] = *(const float4*)(x + (size_t)bn * CC + i * 4);
    __syncthreads();
    for (int h = 0; h < HH; h++) {
        float p = 0.f;
        for (int c = tid; c < CC; c += 128) p = fmaf(sx[c], Wa[h * CC + c], p);
#pragma unroll
        for (int o = 16; o; o >>= 1) p += __shfl_xor_sync(~0u, p, o);
        if ((tid & 31) == 0) warpsum[tid >> 5] = p;
        __syncthreads();
        if (tid == 0) {
            float z = warpsum[0] + warpsum[1] + warpsum[2] + warpsum[3] + ba[h];
            // a = 1 - sigmoid(z) = 1/(1+exp(z))
            float a = (n == 0) ? 1.0f : (1.0f / (1.0f + __expf(z)));
            loga[((size_t)b * HH + h) * NN + n] = logf(a);
        }
        __syncthreads();
    }
}

// ---------------- scan: c[m] = sum_{t<m} log a[t], c[0]=0 ----------------
__global__ void scan_kernel(const float* __restrict__ loga, float* __restrict__ Cex)
{
    int bh = blockIdx.x;
    int t = threadIdx.x;                 // 1024 threads
    __shared__ float buf[NN];
    buf[t] = loga[(size_t)bh * NN + t];
    for (int off = 1; off < NN; off <<= 1) {
        __syncthreads();
        float v = (t >= off) ? buf[t - off] : 0.f;
        __syncthreads();
        buf[t] += v;
    }
    __syncthreads();
    Cex[(size_t)bh * (NN + 1) + t + 1] = buf[t];
    if (t == 0) Cex[(size_t)bh * (NN + 1)] = 0.f;
}

// ---------------- q/k: silu(z)+0.5, L2-normalized over D ----------------
// grid (B*N, H), block 64
__global__ void qknorm_kernel(const float* __restrict__ qkv,
                              float* __restrict__ Qn, float* __restrict__ Kn)
{
    int bn = blockIdx.x;
    int h = blockIdx.y;
    int b = bn >> 10;
    int d = threadIdx.x;
    __shared__ float red[2];
#pragma unroll
    for (int s = 0; s < 2; s++) {
        float z = qkv[(size_t)bn * (3 * CC) + s * CC + h * DD + d];
        float r = z / (1.f + __expf(-z)) + 0.5f;   // silu + 0.5
        float p = r * r;
#pragma unroll
        for (int o = 16; o; o >>= 1) p += __shfl_xor_sync(~0u, p, o);
        if ((d & 31) == 0) red[d >> 5] = p;
        __syncthreads();
        float inv = rsqrtf(red[0] + red[1]);
        float* dst = s ? Kn : Qn;
        dst[(((size_t)b * HH + h) * NN + (size_t)(bn & 1023)) * DD + d] = r * inv;
        __syncthreads();
    }
}

// ---------------- fused lion attention ----------------
// grid (B*H, N/64), block 256 (16x16). Single pass: O = sum_j S*v, r = sum_j S,
// out = O / (r + 1e-6). S = (q.k)*SCALE*exp(delta), delta<=0.
__global__ __launch_bounds__(256) void attn_kernel(
    const float* __restrict__ Q, const float* __restrict__ Kt,
    const float* __restrict__ qkv, const float* __restrict__ Cex,
    float* __restrict__ ctx)
{
    int bh = blockIdx.x;
    int i0 = blockIdx.y * 64;
    int b = bh / HH, h = bh % HH;

    __shared__ float sQ[64][68];   // [d][i]
    __shared__ float sK[64][34];   // [d][j]
    __shared__ float sV[32][64];   // [j][d]
    __shared__ float sS[32][68];   // [j][i]; reused as reduction scratch at end
    __shared__ float scI[65];
    __shared__ float scJ[33];
    __shared__ float srs[64];

    int tid = threadIdx.x;
    int tx = tid & 15, ty = tid >> 4;

    // Q tile (transposed into smem)
#pragma unroll
    for (int l = 0; l < 4; l++) {
        int f = tid + l * 256;          // float4 index 0..1023
        int i = f >> 4, d4 = (f & 15) * 4;
        float4 v = *(const float4*)(Q + (((size_t)bh * NN) + i0 + i) * DD + d4);
        sQ[d4 + 0][i] = v.x; sQ[d4 + 1][i] = v.y;
        sQ[d4 + 2][i] = v.z; sQ[d4 + 3][i] = v.w;
    }
    if (tid < 65) scI[tid] = Cex[(size_t)bh * (NN + 1) + i0 + tid];

    float acc[4][4];
#pragma unroll
    for (int r = 0; r < 4; r++)
#pragma unroll
        for (int c = 0; c < 4; c++) acc[r][c] = 0.f;
    float rs[4] = {0.f, 0.f, 0.f, 0.f};

    const float* vbase = qkv + (size_t)b * NN * (3 * CC) + 2 * CC + h * DD;

    for (int j0 = 0; j0 < NN; j0 += 32) {
        __syncthreads();   // previous stage B done reading sK/sV/sS
        // K tile (transposed) + V tile
#pragma unroll
        for (int l = 0; l < 2; l++) {
            int f = tid + l * 256;      // float4 index 0..511
            int j = f >> 4, d4 = (f & 15) * 4;
            float4 kv = *(const float4*)(Kt + (((size_t)bh * NN) + j0 + j) * DD + d4);
            sK[d4 + 0][j] = kv.x; sK[d4 + 1][j] = kv.y;
            sK[d4 + 2][j] = kv.z; sK[d4 + 3][j] = kv.w;
            float4 vv = *(const float4*)(vbase + (size_t)(j0 + j) * (3 * CC) + d4);
            *(float4*)&sV[j][d4] = vv;
        }
        if (tid < 33) scJ[tid] = Cex[(size_t)bh * (NN + 1) + j0 + tid];
        __syncthreads();

        // Stage A: S[4i x 2j] fragments
        float s[4][2] = {{0.f, 0.f}, {0.f, 0.f}, {0.f, 0.f}, {0.f, 0.f}};
#pragma unroll 16
        for (int d = 0; d < 64; d++) {
            float4 qf = *(const float4*)&sQ[d][ty * 4];
            float2 kf = *(const float2*)&sK[d][tx * 2];
            s[0][0] = fmaf(qf.x, kf.x, s[0][0]); s[0][1] = fmaf(qf.x, kf.y, s[0][1]);
            s[1][0] = fmaf(qf.y, kf.x, s[1][0]); s[1][1] = fmaf(qf.y, kf.y, s[1][1]);
            s[2][0] = fmaf(qf.z, kf.x, s[2][0]); s[2][1] = fmaf(qf.z, kf.y, s[2][1]);
            s[3][0] = fmaf(qf.w, kf.x, s[3][0]); s[3][1] = fmaf(qf.w, kf.y, s[3][1]);
        }
        // Apply mask M, accumulate rowsums, stash S transposed
#pragma unroll
        for (int r = 0; r < 4; r++) {
            int li = ty * 4 + r;
            int gi = i0 + li;
#pragma unroll
            for (int u = 0; u < 2; u++) {
                int lj = tx * 2 + u;
                int gj = j0 + lj;
                float delta;
                if (gj < gi)      delta = scI[li] - scJ[lj];          // c[i]-c[j]
                else if (gj > gi) delta = scJ[lj + 1] - scI[li + 1];  // c[j+1]-c[i+1]
                else              delta = 0.f;
                float val = s[r][u] * SCALE * fexp(delta);
                rs[r] += val;
                sS[lj][li] = val;
            }
        }
        __syncthreads();

        // Stage B: acc[4i x 4d] += S_tile @ V_tile
#pragma unroll 8
        for (int jj = 0; jj < 32; jj++) {
            float4 sf = *(const float4*)&sS[jj][ty * 4];
            float4 vf = *(const float4*)&sV[jj][tx * 4];
            acc[0][0] = fmaf(sf.x, vf.x, acc[0][0]); acc[0][1] = fmaf(sf.x, vf.y, acc[0][1]);
            acc[0][2] = fmaf(sf.x, vf.z, acc[0][2]); acc[0][3] = fmaf(sf.x, vf.w, acc[0][3]);
            acc[1][0] = fmaf(sf.y, vf.x, acc[1][0]); acc[1][1] = fmaf(sf.y, vf.y, acc[1][1]);
            acc[1][2] = fmaf(sf.y, vf.z, acc[1][2]); acc[1][3] = fmaf(sf.y, vf.w, acc[1][3]);
            acc[2][0] = fmaf(sf.z, vf.x, acc[2][0]); acc[2][1] = fmaf(sf.z, vf.y, acc[2][1]);
            acc[2][2] = fmaf(sf.z, vf.z, acc[2][2]); acc[2][3] = fmaf(sf.z, vf.w, acc[2][3]);
            acc[3][0] = fmaf(sf.w, vf.x, acc[3][0]); acc[3][1] = fmaf(sf.w, vf.y, acc[3][1]);
            acc[3][2] = fmaf(sf.w, vf.z, acc[3][2]); acc[3][3] = fmaf(sf.w, vf.w, acc[3][3]);
        }
    }

    // Reduce row sums across tx (16 partials per row)
    __syncthreads();
    float* red = &sS[0][0];
#pragma unroll
    for (int r = 0; r < 4; r++) red[(ty * 4 + r) * 16 + tx] = rs[r];
    __syncthreads();
    if (tid < 64) {
        float sum = 0.f;
#pragma unroll
        for (int t = 0; t < 16; t++) sum += red[tid * 16 + t];
        srs[tid] = 1.0f / (sum + 1e-6f);
    }
    __syncthreads();

    // Normalize and write ctx[b, i0+i, h*64 + d]
#pragma unroll
    for (int r = 0; r < 4; r++) {
        int li = ty * 4 + r;
        float inv = srs[li];
        float4 o;
        o.x = acc[r][0] * inv; o.y = acc[r][1] * inv;
        o.z = acc[r][2] * inv; o.w = acc[r][3] * inv;
        *(float4*)(ctx + ((size_t)b * NN + i0 + li) * CC + h * DD + tx * 4) = o;
    }
}

// ---------------- launch ----------------
extern "C" void kernel_launch(void* const* d_in, const int* in_sizes, int n_in,
                              void* d_out, int out_size)
{
    (void)in_sizes; (void)n_in; (void)out_size;
    const float* x     = (const float*)d_in[0];
    const float* Wqkv  = (const float*)d_in[1];
    const float* Wa    = (const float*)d_in[2];
    const float* ba    = (const float*)d_in[3];
    const float* Wproj = (const float*)d_in[4];
    const float* bproj = (const float*)d_in[5];
    float* out = (float*)d_out;

    void *p_qkv, *p_q, *p_k, *p_loga, *p_c, *p_ctx;
    cudaGetSymbolAddress(&p_qkv, g_qkv);
    cudaGetSymbolAddress(&p_q, g_q);
    cudaGetSymbolAddress(&p_k, g_k);
    cudaGetSymbolAddress(&p_loga, g_loga);
    cudaGetSymbolAddress(&p_c, g_c);
    cudaGetSymbolAddress(&p_ctx, g_ctx);

    float* qkv  = (float*)p_qkv;
    float* q    = (float*)p_q;
    float* k    = (float*)p_k;
    float* loga = (float*)p_loga;
    float* cex  = (float*)p_c;
    float* ctx  = (float*)p_ctx;

    // 1) qkv = x @ Wqkv^T   [2048 x 2304]
    sgemm_nt<<<dim3(3 * CC / 128, BB * NN / 128), 256>>>(x, Wqkv, nullptr, qkv,
                                                          BB * NN, 3 * CC, CC);
    // 2) gate logits -> log(a)
    gate_kernel<<<BB * NN, 128>>>(x, Wa, ba, loga);
    // 3) prefix scan -> c
    scan_kernel<<<BB * HH, NN>>>(loga, cex);
    // 4) q/k silu+0.5 L2-norm
    qknorm_kernel<<<dim3(BB * NN, HH), DD>>>(qkv, q, k);
    // 5) fused attention -> ctx
    attn_kernel<<<dim3(BB * HH, NN / 64), 256>>>(q, k, qkv, cex, ctx);
    // 6) out = ctx @ Wproj^T + bproj
    sgemm_nt<<<dim3(CC / 128, BB * NN / 128), 256>>>(ctx, Wproj, bproj, out,
                                                      BB * NN, CC, CC);
}

// round 2
// speedup vs baseline: 3.9746x; 3.9746x over previous
#include <cuda_runtime.h>
#include <cuda_bf16.h>
#include <cstdint>
#include <math.h>

#define BB 2
#define NN 1024
#define CC 768
#define HH 12
#define DD 64
#define SCALE 0.125f

// ---------------- scratch ----------------
__device__ float g_qkv[BB * NN * 3 * CC];
__device__ float g_q[BB * HH * NN * DD];
__device__ float g_k[BB * HH * NN * DD];
__device__ float g_loga[BB * HH * NN];
__device__ float g_c[BB * HH * (NN + 1)];
__device__ float g_ctx[BB * NN * CC];

// ---------------- tf32 helpers ----------------
__device__ __forceinline__ uint32_t f2tf(float x) {
    uint32_t r; asm("cvt.rna.tf32.f32 %0, %1;" : "=r"(r) : "f"(x)); return r;
}
__device__ __forceinline__ void mma8(float* d, const uint32_t* a, const uint32_t* b) {
    asm volatile(
        "mma.sync.aligned.m16n8k8.row.col.f32.tf32.tf32.f32 "
        "{%0,%1,%2,%3},{%4,%5,%6,%7},{%8,%9},{%0,%1,%2,%3};"
        : "+f"(d[0]), "+f"(d[1]), "+f"(d[2]), "+f"(d[3])
        : "r"(a[0]), "r"(a[1]), "r"(a[2]), "r"(a[3]), "r"(b[0]), "r"(b[1]));
}

// ---------------- tf32 GEMM: C[M,N] = A[M,K] @ W[N,K]^T (+bias) ----------------
// 128x128 tile, BK=16, 256 threads = 8 warps (2m x 4n), warp tile 64x32.
#define GBM 128
#define GBN 128
#define GBK 16
#define GST (GBK + 4)   // smem row stride (uint32): 20 -> frag loads conflict-free
__global__ __launch_bounds__(256, 2) void gemm_tf32(
    const float* __restrict__ A, const float* __restrict__ W,
    const float* __restrict__ bias, float* __restrict__ C,
    int M, int N, int K)
{
    __shared__ uint32_t sA[GBM][GST];
    __shared__ uint32_t sB[GBN][GST];
    int tid = threadIdx.x;
    int lane = tid & 31, warp = tid >> 5;
    int g = lane >> 2, t = lane & 3;
    int wm = (warp & 1) * 64;
    int wn = (warp >> 1) * 32;
    int bm = blockIdx.y * GBM, bn = blockIdx.x * GBN;

    float acc[4][4][4];
#pragma unroll
    for (int i = 0; i < 4; i++)
#pragma unroll
        for (int j = 0; j < 4; j++)
#pragma unroll
            for (int r = 0; r < 4; r++) acc[i][j][r] = 0.f;

    int lr = tid >> 1;
    int lk = (tid & 1) * 8;
    const float* Ap = A + (size_t)(bm + lr) * K + lk;
    const float* Wp = W + (size_t)(bn + lr) * K + lk;

    float4 ra0 = *(const float4*)(Ap);
    float4 ra1 = *(const float4*)(Ap + 4);
    float4 rb0 = *(const float4*)(Wp);
    float4 rb1 = *(const float4*)(Wp + 4);

    for (int k0 = 0; k0 < K; k0 += GBK) {
        __syncthreads();
        *(uint4*)&sA[lr][lk]     = make_uint4(f2tf(ra0.x), f2tf(ra0.y), f2tf(ra0.z), f2tf(ra0.w));
        *(uint4*)&sA[lr][lk + 4] = make_uint4(f2tf(ra1.x), f2tf(ra1.y), f2tf(ra1.z), f2tf(ra1.w));
        *(uint4*)&sB[lr][lk]     = make_uint4(f2tf(rb0.x), f2tf(rb0.y), f2tf(rb0.z), f2tf(rb0.w));
        *(uint4*)&sB[lr][lk + 4] = make_uint4(f2tf(rb1.x), f2tf(rb1.y), f2tf(rb1.z), f2tf(rb1.w));
        __syncthreads();
        if (k0 + GBK < K) {
            ra0 = *(const float4*)(Ap + k0 + GBK);
            ra1 = *(const float4*)(Ap + k0 + GBK + 4);
            rb0 = *(const float4*)(Wp + k0 + GBK);
            rb1 = *(const float4*)(Wp + k0 + GBK + 4);
        }
#pragma unroll
        for (int kc = 0; kc < GBK; kc += 8) {
            uint32_t af[4][4];
#pragma unroll
            for (int mt = 0; mt < 4; mt++) {
                int m = wm + mt * 16;
                af[mt][0] = sA[m + g][kc + t];
                af[mt][1] = sA[m + g + 8][kc + t];
                af[mt][2] = sA[m + g][kc + t + 4];
                af[mt][3] = sA[m + g + 8][kc + t + 4];
            }
            uint32_t bf[4][2];
#pragma unroll
            for (int nt = 0; nt < 4; nt++) {
                bf[nt][0] = sB[wn + nt * 8 + g][kc + t];
                bf[nt][1] = sB[wn + nt * 8 + g][kc + t + 4];
            }
#pragma unroll
            for (int mt = 0; mt < 4; mt++)
#pragma unroll
                for (int nt = 0; nt < 4; nt++)
                    mma8(acc[mt][nt], af[mt], bf[nt]);
        }
    }

#pragma unroll
    for (int mt = 0; mt < 4; mt++) {
#pragma unroll
        for (int nt = 0; nt < 4; nt++) {
            int row = bm + wm + mt * 16 + g;
            int col = bn + wn + nt * 8 + t * 2;
            float b0 = bias ? bias[col] : 0.f;
            float b1 = bias ? bias[col + 1] : 0.f;
            float2 o0 = make_float2(acc[mt][nt][0] + b0, acc[mt][nt][1] + b1);
            float2 o1 = make_float2(acc[mt][nt][2] + b0, acc[mt][nt][3] + b1);
            *(float2*)(C + (size_t)row * N + col) = o0;
            *(float2*)(C + (size_t)(row + 8) * N + col) = o1;
        }
    }
}

// ---------------- gate: loga[b*H+h][n] ----------------
__global__ __launch_bounds__(128) void gate_kernel(
    const float* __restrict__ x, const float* __restrict__ Wa,
    const float* __restrict__ ba, float* __restrict__ loga)
{
    int bn = blockIdx.x;
    int b = bn >> 10, n = bn & 1023;
    __shared__ float sx[CC];
    int tid = threadIdx.x, warp = tid >> 5, lane = tid & 31;
    for (int i = tid; i < CC / 4; i += 128)
        *(float4*)&sx[i * 4] = *(const float4*)(x + (size_t)bn * CC + i * 4);
    __syncthreads();
    for (int h = warp; h < HH; h += 4) {
        float p = 0.f;
        for (int c = lane; c < CC; c += 32) p = fmaf(sx[c], Wa[h * CC + c], p);
#pragma unroll
        for (int o = 16; o; o >>= 1) p += __shfl_xor_sync(~0u, p, o);
        if (lane == 0) {
            float z = p + ba[h];
            // log a = log(1/(1+e^z)) computed stably
            float la = -(fmaxf(z, 0.f) + log1pf(__expf(-fabsf(z))));
            loga[((size_t)b * HH + h) * NN + n] = (n == 0) ? 0.f : la;
        }
    }
}

// ---------------- scan: exclusive prefix of log a ----------------
__global__ void scan_kernel(const float* __restrict__ loga, float* __restrict__ Cex)
{
    int bh = blockIdx.x;
    int t = threadIdx.x;
    __shared__ float buf[NN];
    buf[t] = loga[(size_t)bh * NN + t];
    for (int off = 1; off < NN; off <<= 1) {
        __syncthreads();
        float v = (t >= off) ? buf[t - off] : 0.f;
        __syncthreads();
        buf[t] += v;
    }
    __syncthreads();
    Cex[(size_t)bh * (NN + 1) + t + 1] = buf[t];
    if (t == 0) Cex[(size_t)bh * (NN + 1)] = 0.f;
}

// ---------------- qk norm: warp per head, no block syncs ----------------
__global__ __launch_bounds__(384) void qknorm_kernel(
    const float* __restrict__ qkv, float* __restrict__ Qn, float* __restrict__ Kn)
{
    int bn = blockIdx.x;
    int s = blockIdx.y;                  // 0 = q, 1 = k
    int h = threadIdx.x >> 5, lane = threadIdx.x & 31;
    const float* src = qkv + (size_t)bn * (3 * CC) + s * CC + h * DD;
    float z0 = src[lane], z1 = src[lane + 32];
    float r0 = z0 / (1.f + __expf(-z0)) + 0.5f;
    float r1 = z1 / (1.f + __expf(-z1)) + 0.5f;
    float p = r0 * r0 + r1 * r1;
#pragma unroll
    for (int o = 16; o; o >>= 1) p += __shfl_xor_sync(~0u, p, o);
    float inv = rsqrtf(p);
    float* dst = (s ? Kn : Qn) +
        (((size_t)(bn >> 10) * HH + h) * NN + (size_t)(bn & 1023)) * DD;
    dst[lane] = r0 * inv;
    dst[lane + 32] = r1 * inv;
}

// ---------------- fused attention, tf32 MMA both stages ----------------
// grid (B*H, N/64), 128 threads = 4 warps; warp w owns rows [64*blk + 16w, +16).
__global__ __launch_bounds__(128) void attn_tf32(
    const float* __restrict__ Q, const float* __restrict__ Kt,
    const float* __restrict__ qkv, const float* __restrict__ Cex,
    float* __restrict__ ctx)
{
    int bh = blockIdx.x;
    int i0 = blockIdx.y * 64;
    int b = bh / HH, h = bh % HH;

    __shared__ uint32_t sQ[64][68];   // [i][d] tf32, pre-scaled
    __shared__ uint32_t sK[32][68];   // [j][d] tf32
    __shared__ uint32_t sVt[64][36];  // [d][j^swz] tf32
    __shared__ uint32_t sS[64][36];   // [i][j] tf32 (masked S)
    __shared__ float scI[65];
    __shared__ float scJ[33];

    int tid = threadIdx.x;
    int lane = tid & 31, warp = tid >> 5;
    int g = lane >> 2, t = lane & 3;
    int iw = warp * 16;

    // Q tile (pre-scaled by SCALE)
#pragma unroll
    for (int l = 0; l < 8; l++) {
        int f = tid + l * 128;
        int i = f >> 4, d4 = (f & 15) * 4;
        float4 v = *(const float4*)(Q + (((size_t)bh * NN) + i0 + i) * DD + d4);
        *(uint4*)&sQ[i][d4] = make_uint4(f2tf(v.x * SCALE), f2tf(v.y * SCALE),
                                         f2tf(v.z * SCALE), f2tf(v.w * SCALE));
    }
    if (tid < 65) scI[tid] = Cex[(size_t)bh * (NN + 1) + i0 + tid];

    float oacc[8][4];
#pragma unroll
    for (int nt = 0; nt < 8; nt++)
#pragma unroll
        for (int r = 0; r < 4; r++) oacc[nt][r] = 0.f;
    float rs0 = 0.f, rs1 = 0.f;

    const float* vbase = qkv + (size_t)b * NN * (3 * CC) + 2 * CC + h * DD;

    float cI0 = 0.f, cI0n = 0.f, cI1 = 0.f, cI1n = 0.f;
    int gi0 = i0 + iw + g, gi1 = gi0 + 8;

    for (int j0 = 0; j0 < NN; j0 += 32) {
        __syncthreads();
        // load K (row layout) and V (transposed, swizzled)
#pragma unroll
        for (int l = 0; l < 4; l++) {
            int f = tid + l * 128;
            int j = f >> 4, d4 = (f & 15) * 4;
            float4 kv = *(const float4*)(Kt + (((size_t)bh * NN) + j0 + j) * DD + d4);
            *(uint4*)&sK[j][d4] = make_uint4(f2tf(kv.x), f2tf(kv.y), f2tf(kv.z), f2tf(kv.w));
            float4 vv = *(const float4*)(vbase + (size_t)(j0 + j) * (3 * CC) + d4);
            sVt[d4 + 0][j ^ (((d4 + 0) >> 3) & 7)] = f2tf(vv.x);
            sVt[d4 + 1][j ^ (((d4 + 1) >> 3) & 7)] = f2tf(vv.y);
            sVt[d4 + 2][j ^ (((d4 + 2) >> 3) & 7)] = f2tf(vv.z);
            sVt[d4 + 3][j ^ (((d4 + 3) >> 3) & 7)] = f2tf(vv.w);
        }
        if (tid < 33) scJ[tid] = Cex[(size_t)bh * (NN + 1) + j0 + tid];
        if (j0 == 0) {
            cI0 = scI[iw + g];  cI0n = scI[iw + g + 1];
            cI1 = scI[iw + g + 8]; cI1n = scI[iw + g + 9];
        }
        __syncthreads();

        // Stage A: S[16 x 32] = Q_w @ K^T
        float sf[4][4];
#pragma unroll
        for (int nt = 0; nt < 4; nt++)
#pragma unroll
            for (int r = 0; r < 4; r++) sf[nt][r] = 0.f;
#pragma unroll
        for (int kc = 0; kc < 64; kc += 8) {
            uint32_t af[4] = { sQ[iw + g][kc + t], sQ[iw + g + 8][kc + t],
                               sQ[iw + g][kc + t + 4], sQ[iw + g + 8][kc + t + 4] };
#pragma unroll
            for (int nt = 0; nt < 4; nt++) {
                uint32_t bf[2] = { sK[nt * 8 + g][kc + t], sK[nt * 8 + g][kc + t + 4] };
                mma8(sf[nt], af, bf);
            }
        }

        // mask * exp, rowsum, stash S (tf32)
#pragma unroll
        for (int nt = 0; nt < 4; nt++) {
#pragma unroll
            for (int e = 0; e < 2; e++) {
                int lj = nt * 8 + t * 2 + e;
                int gj = j0 + lj;
                float cJ = scJ[lj], cJn = scJ[lj + 1];
                float d0 = (gj < gi0) ? (cI0 - cJ) : ((gj > gi0) ? (cJn - cI0n) : 0.f);
                float v0 = sf[nt][e] * __expf(d0);
                rs0 += v0;
                sS[iw + g][lj] = f2tf(v0);
                float d1 = (gj < gi1) ? (cI1 - cJ) : ((gj > gi1) ? (cJn - cI1n) : 0.f);
                float v1 = sf[nt][2 + e] * __expf(d1);
                rs1 += v1;
                sS[iw + g + 8][lj] = f2tf(v1);
            }
        }
        __syncthreads();

        // Stage B: O[16 x 64] += S[16 x 32] @ V[32 x 64]
#pragma unroll
        for (int kc = 0; kc < 32; kc += 8) {
            uint32_t af[4] = { sS[iw + g][kc + t], sS[iw + g + 8][kc + t],
                               sS[iw + g][kc + t + 4], sS[iw + g + 8][kc + t + 4] };
#pragma unroll
            for (int nt = 0; nt < 8; nt++) {
                int sw = nt & 7;
                uint32_t bf[2] = { sVt[nt * 8 + g][(kc + t) ^ sw],
                                   sVt[nt * 8 + g][(kc + t + 4) ^ sw] };
                mma8(oacc[nt], af, bf);
            }
        }
    }

    // reduce row sums across the 4 lanes sharing each row
    rs0 += __shfl_xor_sync(~0u, rs0, 1);
    rs0 += __shfl_xor_sync(~0u, rs0, 2);
    rs1 += __shfl_xor_sync(~0u, rs1, 1);
    rs1 += __shfl_xor_sync(~0u, rs1, 2);
    float inv0 = 1.f / (rs0 + 1e-6f);
    float inv1 = 1.f / (rs1 + 1e-6f);

#pragma unroll
    for (int nt = 0; nt < 8; nt++) {
        int col = h * DD + nt * 8 + t * 2;
        float2 o0 = make_float2(oacc[nt][0] * inv0, oacc[nt][1] * inv0);
        float2 o1 = make_float2(oacc[nt][2] * inv1, oacc[nt][3] * inv1);
        *(float2*)(ctx + ((size_t)b * NN + gi0) * CC + col) = o0;
        *(float2*)(ctx + ((size_t)b * NN + gi1) * CC + col) = o1;
    }
}

// ---------------- launch ----------------
extern "C" void kernel_launch(void* const* d_in, const int* in_sizes, int n_in,
                              void* d_out, int out_size)
{
    (void)in_sizes; (void)n_in; (void)out_size;
    const float* x     = (const float*)d_in[0];
    const float* Wqkv  = (const float*)d_in[1];
    const float* Wa    = (const float*)d_in[2];
    const float* ba    = (const float*)d_in[3];
    const float* Wproj = (const float*)d_in[4];
    const float* bproj = (const float*)d_in[5];
    float* out = (float*)d_out;

    void *p_qkv, *p_q, *p_k, *p_loga, *p_c, *p_ctx;
    cudaGetSymbolAddress(&p_qkv, g_qkv);
    cudaGetSymbolAddress(&p_q, g_q);
    cudaGetSymbolAddress(&p_k, g_k);
    cudaGetSymbolAddress(&p_loga, g_loga);
    cudaGetSymbolAddress(&p_c, g_c);
    cudaGetSymbolAddress(&p_ctx, g_ctx);

    float* qkv  = (float*)p_qkv;
    float* q    = (float*)p_q;
    float* k    = (float*)p_k;
    float* loga = (float*)p_loga;
    float* cex  = (float*)p_c;
    float* ctx  = (float*)p_ctx;

    gemm_tf32<<<dim3(3 * CC / GBN, BB * NN / GBM), 256>>>(x, Wqkv, nullptr, qkv,
                                                          BB * NN, 3 * CC, CC);
    gate_kernel<<<BB * NN, 128>>>(x, Wa, ba, loga);
    scan_kernel<<<BB * HH, NN>>>(loga, cex);
    qknorm_kernel<<<dim3(BB * NN, 2), 384>>>(qkv, q, k);
    attn_tf32<<<dim3(BB * HH, NN / 64), 128>>>(q, k, qkv, cex, ctx);
    gemm_tf32<<<dim3(CC / GBN, BB * NN / GBM), 256>>>(ctx, Wproj, bproj, out,
                                                      BB * NN, CC, CC);
}

// round 3
// speedup vs baseline: 4.5282x; 1.1393x over previous
#include <cuda_runtime.h>
#include <cuda_bf16.h>
#include <cstdint>
#include <math.h>

#define BB 2
#define NN 1024
#define CC 768
#define HH 12
#define DD 64
#define SCALE 0.125f

// ---------------- scratch ----------------
__device__ float g_qkv[BB * NN * 3 * CC];
__device__ float g_q[BB * HH * NN * DD];
__device__ float g_k[BB * HH * NN * DD];
__device__ float g_loga[BB * HH * NN];
__device__ float g_c[BB * HH * (NN + 1)];
__device__ float g_ctx[BB * NN * CC];

// ---------------- tf32 helpers ----------------
__device__ __forceinline__ uint32_t f2tf(float x) {
    uint32_t r; asm("cvt.rna.tf32.f32 %0, %1;" : "=r"(r) : "f"(x)); return r;
}
__device__ __forceinline__ void mma8(float* d, const uint32_t* a, const uint32_t* b) {
    asm volatile(
        "mma.sync.aligned.m16n8k8.row.col.f32.tf32.tf32.f32 "
        "{%0,%1,%2,%3},{%4,%5,%6,%7},{%8,%9},{%0,%1,%2,%3};"
        : "+f"(d[0]), "+f"(d[1]), "+f"(d[2]), "+f"(d[3])
        : "r"(a[0]), "r"(a[1]), "r"(a[2]), "r"(a[3]), "r"(b[0]), "r"(b[1]));
}
__device__ __forceinline__ void ldsm4(uint32_t* r, uint32_t addr) {
    asm volatile("ldmatrix.sync.aligned.m8n8.x4.shared.b16 {%0,%1,%2,%3}, [%4];"
        : "=r"(r[0]), "=r"(r[1]), "=r"(r[2]), "=r"(r[3]) : "r"(addr));
}

// ---------------- tf32 GEMM: C[M,N] = A[M,K] @ W[N,K]^T (+bias) ----------------
#define GBM 128
#define GBN 128
#define GBK 16
#define GST 20
__global__ __launch_bounds__(256, 2) void gemm_tf32(
    const float* __restrict__ A, const float* __restrict__ W,
    const float* __restrict__ bias, float* __restrict__ C,
    int M, int N, int K)
{
    __shared__ uint32_t sA[GBM][GST];
    __shared__ uint32_t sB[GBN][GST];
    int tid = threadIdx.x;
    int lane = tid & 31, warp = tid >> 5;
    int g = lane >> 2, t = lane & 3;
    int wm = (warp & 1) * 64;
    int wn = (warp >> 1) * 32;
    int bm = blockIdx.y * GBM, bn = blockIdx.x * GBN;

    float acc[4][4][4];
#pragma unroll
    for (int i = 0; i < 4; i++)
#pragma unroll
        for (int j = 0; j < 4; j++)
#pragma unroll
            for (int r = 0; r < 4; r++) acc[i][j][r] = 0.f;

    int lr = tid >> 1;
    int lk = (tid & 1) * 8;
    const float* Ap = A + (size_t)(bm + lr) * K + lk;
    const float* Wp = W + (size_t)(bn + lr) * K + lk;

    // ldmatrix lane addresses
    uint32_t baseA = (uint32_t)__cvta_generic_to_shared(&sA[0][0]);
    uint32_t baseB = (uint32_t)__cvta_generic_to_shared(&sB[0][0]);
    int r8 = ((lane >> 3) & 1) * 8 + (lane & 7);
    int q4 = (lane >> 4) * 4;
    int rB = (lane >> 4) * 8 + (lane & 7);
    int cB4 = ((lane >> 3) & 1) * 4;
    uint32_t aaddr = baseA + (uint32_t)(((wm + r8) * GST + q4) * 4);
    uint32_t baddr = baseB + (uint32_t)(((wn + rB) * GST + cB4) * 4);

    float4 ra0 = *(const float4*)(Ap);
    float4 ra1 = *(const float4*)(Ap + 4);
    float4 rb0 = *(const float4*)(Wp);
    float4 rb1 = *(const float4*)(Wp + 4);

    for (int k0 = 0; k0 < K; k0 += GBK) {
        __syncthreads();
        *(uint4*)&sA[lr][lk]     = make_uint4(f2tf(ra0.x), f2tf(ra0.y), f2tf(ra0.z), f2tf(ra0.w));
        *(uint4*)&sA[lr][lk + 4] = make_uint4(f2tf(ra1.x), f2tf(ra1.y), f2tf(ra1.z), f2tf(ra1.w));
        *(uint4*)&sB[lr][lk]     = make_uint4(f2tf(rb0.x), f2tf(rb0.y), f2tf(rb0.z), f2tf(rb0.w));
        *(uint4*)&sB[lr][lk + 4] = make_uint4(f2tf(rb1.x), f2tf(rb1.y), f2tf(rb1.z), f2tf(rb1.w));
        __syncthreads();
        if (k0 + GBK < K) {
            ra0 = *(const float4*)(Ap + k0 + GBK);
            ra1 = *(const float4*)(Ap + k0 + GBK + 4);
            rb0 = *(const float4*)(Wp + k0 + GBK);
            rb1 = *(const float4*)(Wp + k0 + GBK + 4);
        }
#pragma unroll
        for (int kc = 0; kc < GBK; kc += 8) {
            uint32_t af[4][4];
#pragma unroll
            for (int mt = 0; mt < 4; mt++)
                ldsm4(af[mt], aaddr + (uint32_t)((mt * 16 * GST + kc) * 4));
            uint32_t bf[2][4];
#pragma unroll
            for (int p = 0; p < 2; p++)
                ldsm4(bf[p], baddr + (uint32_t)((p * 16 * GST + kc) * 4));
#pragma unroll
            for (int mt = 0; mt < 4; mt++) {
                mma8(acc[mt][0], af[mt], bf[0]);
                mma8(acc[mt][1], af[mt], bf[0] + 2);
                mma8(acc[mt][2], af[mt], bf[1]);
                mma8(acc[mt][3], af[mt], bf[1] + 2);
            }
        }
    }

#pragma unroll
    for (int mt = 0; mt < 4; mt++) {
#pragma unroll
        for (int nt = 0; nt < 4; nt++) {
            int row = bm + wm + mt * 16 + g;
            int col = bn + wn + nt * 8 + t * 2;
            float b0 = bias ? bias[col] : 0.f;
            float b1 = bias ? bias[col + 1] : 0.f;
            float2 o0 = make_float2(acc[mt][nt][0] + b0, acc[mt][nt][1] + b1);
            float2 o1 = make_float2(acc[mt][nt][2] + b0, acc[mt][nt][3] + b1);
            *(float2*)(C + (size_t)row * N + col) = o0;
            *(float2*)(C + (size_t)(row + 8) * N + col) = o1;
        }
    }
}

// ---------------- gate ----------------
__global__ __launch_bounds__(128) void gate_kernel(
    const float* __restrict__ x, const float* __restrict__ Wa,
    const float* __restrict__ ba, float* __restrict__ loga)
{
    int bn = blockIdx.x;
    int b = bn >> 10, n = bn & 1023;
    __shared__ float sx[CC];
    int tid = threadIdx.x, warp = tid >> 5, lane = tid & 31;
    for (int i = tid; i < CC / 4; i += 128)
        *(float4*)&sx[i * 4] = *(const float4*)(x + (size_t)bn * CC + i * 4);
    __syncthreads();
    for (int h = warp; h < HH; h += 4) {
        float p = 0.f;
        for (int c = lane; c < CC; c += 32) p = fmaf(sx[c], Wa[h * CC + c], p);
#pragma unroll
        for (int o = 16; o; o >>= 1) p += __shfl_xor_sync(~0u, p, o);
        if (lane == 0) {
            float z = p + ba[h];
            float la = -(fmaxf(z, 0.f) + log1pf(__expf(-fabsf(z))));
            loga[((size_t)b * HH + h) * NN + n] = (n == 0) ? 0.f : la;
        }
    }
}

// ---------------- scan (warp shuffles, 2 barriers) ----------------
__global__ void scan_kernel(const float* __restrict__ loga, float* __restrict__ Cex)
{
    int bh = blockIdx.x;
    int t = threadIdx.x, lane = t & 31, w = t >> 5;
    __shared__ float wsum[32];
    float s = loga[(size_t)bh * NN + t];
#pragma unroll
    for (int o = 1; o < 32; o <<= 1) {
        float u = __shfl_up_sync(~0u, s, o);
        if (lane >= o) s += u;
    }
    if (lane == 31) wsum[w] = s;
    __syncthreads();
    if (w == 0) {
        float ws = wsum[lane];
#pragma unroll
        for (int o = 1; o < 32; o <<= 1) {
            float u = __shfl_up_sync(~0u, ws, o);
            if (lane >= o) ws += u;
        }
        wsum[lane] = ws;
    }
    __syncthreads();
    float base = w ? wsum[w - 1] : 0.f;
    Cex[(size_t)bh * (NN + 1) + t + 1] = s + base;
    if (t == 0) Cex[(size_t)bh * (NN + 1)] = 0.f;
}

// ---------------- qk norm ----------------
__global__ __launch_bounds__(384) void qknorm_kernel(
    const float* __restrict__ qkv, float* __restrict__ Qn, float* __restrict__ Kn)
{
    int bn = blockIdx.x;
    int s = blockIdx.y;
    int h = threadIdx.x >> 5, lane = threadIdx.x & 31;
    const float* src = qkv + (size_t)bn * (3 * CC) + s * CC + h * DD;
    float z0 = src[lane], z1 = src[lane + 32];
    float r0 = z0 / (1.f + __expf(-z0)) + 0.5f;
    float r1 = z1 / (1.f + __expf(-z1)) + 0.5f;
    float p = r0 * r0 + r1 * r1;
#pragma unroll
    for (int o = 16; o; o >>= 1) p += __shfl_xor_sync(~0u, p, o);
    float inv = rsqrtf(p);
    float* dst = (s ? Kn : Qn) +
        (((size_t)(bn >> 10) * HH + h) * NN + (size_t)(bn & 1023)) * DD;
    dst[lane] = r0 * inv;
    dst[lane + 32] = r1 * inv;
}

// ---------------- fused attention (ldmatrix + conflict-free V transpose) ----------------
__global__ __launch_bounds__(128) void attn_tf32(
    const float* __restrict__ Q, const float* __restrict__ Kt,
    const float* __restrict__ qkv, const float* __restrict__ Cex,
    float* __restrict__ ctx)
{
    int bh = blockIdx.x;
    int i0 = blockIdx.y * 64;
    int b = bh / HH, h = bh % HH;

    __shared__ uint32_t sQ[64][68];   // [i][d] tf32, pre-scaled
    __shared__ uint32_t sK[32][68];   // [j][d] tf32
    __shared__ uint32_t sVt[64][36];  // [d][j] tf32 (plain padded, conflict-free)
    __shared__ uint32_t sS[64][36];   // [i][j] tf32
    __shared__ float scI[65];
    __shared__ float scJ[33];

    int tid = threadIdx.x;
    int lane = tid & 31, warp = tid >> 5;
    int g = lane >> 2, t = lane & 3;
    int iw = warp * 16;

    // ldmatrix lane addresses
    uint32_t baseQ = (uint32_t)__cvta_generic_to_shared(&sQ[0][0]);
    uint32_t baseK = (uint32_t)__cvta_generic_to_shared(&sK[0][0]);
    uint32_t baseV = (uint32_t)__cvta_generic_to_shared(&sVt[0][0]);
    uint32_t baseS = (uint32_t)__cvta_generic_to_shared(&sS[0][0]);
    int r8 = ((lane >> 3) & 1) * 8 + (lane & 7);
    int q4 = (lane >> 4) * 4;
    int rB = (lane >> 4) * 8 + (lane & 7);
    int cB4 = ((lane >> 3) & 1) * 4;
    uint32_t aQaddr = baseQ + (uint32_t)(((iw + r8) * 68 + q4) * 4);
    uint32_t aSaddr = baseS + (uint32_t)(((iw + r8) * 36 + q4) * 4);
    uint32_t bKaddr = baseK + (uint32_t)((rB * 68 + cB4) * 4);
    uint32_t bVaddr = baseV + (uint32_t)((rB * 36 + cB4) * 4);

    // Q tile (pre-scaled by SCALE)
#pragma unroll
    for (int l = 0; l < 8; l++) {
        int f = tid + l * 128;
        int i = f >> 4, d4 = (f & 15) * 4;
        float4 v = *(const float4*)(Q + (((size_t)bh * NN) + i0 + i) * DD + d4);
        *(uint4*)&sQ[i][d4] = make_uint4(f2tf(v.x * SCALE), f2tf(v.y * SCALE),
                                         f2tf(v.z * SCALE), f2tf(v.w * SCALE));
    }
    if (tid < 65) scI[tid] = Cex[(size_t)bh * (NN + 1) + i0 + tid];

    float oacc[8][4];
#pragma unroll
    for (int nt = 0; nt < 8; nt++)
#pragma unroll
        for (int r = 0; r < 4; r++) oacc[nt][r] = 0.f;
    float rs0 = 0.f, rs1 = 0.f;

    const float* vbase = qkv + (size_t)b * NN * (3 * CC) + 2 * CC + h * DD;

    float cI0 = 0.f, cI0n = 0.f, cI1 = 0.f, cI1n = 0.f;
    int gi0 = i0 + iw + g, gi1 = gi0 + 8;

    int dv = (warp & 1) * 32 + lane;      // d column owned for V transpose
    int qv = warp >> 1;                   // j-quad group

    for (int j0 = 0; j0 < NN; j0 += 32) {
        __syncthreads();
        // K tile: [j][d], cvt on store
#pragma unroll
        for (int l = 0; l < 4; l++) {
            int f = tid + l * 128;        // 0..511 float4s
            int j = f >> 4, d4 = (f & 15) * 4;
            float4 kv = *(const float4*)(Kt + (((size_t)bh * NN) + j0 + j) * DD + d4);
            *(uint4*)&sK[j][d4] = make_uint4(f2tf(kv.x), f2tf(kv.y), f2tf(kv.z), f2tf(kv.w));
        }
        // V tile transposed: lane owns column dv, writes STS.128 (conflict-free)
#pragma unroll
        for (int l = 0; l < 4; l++) {
            int j4 = (qv * 4 + l) * 4;
            const float* vp = vbase + (size_t)(j0 + j4) * (3 * CC) + dv;
            uint32_t w0 = f2tf(vp[0]);
            uint32_t w1 = f2tf(vp[3 * CC]);
            uint32_t w2 = f2tf(vp[6 * CC]);
            uint32_t w3 = f2tf(vp[9 * CC]);
            *(uint4*)&sVt[dv][j4] = make_uint4(w0, w1, w2, w3);
        }
        if (tid < 33) scJ[tid] = Cex[(size_t)bh * (NN + 1) + j0 + tid];
        if (j0 == 0) {
            cI0 = scI[iw + g];     cI0n = scI[iw + g + 1];
            cI1 = scI[iw + g + 8]; cI1n = scI[iw + g + 9];
        }
        __syncthreads();

        // Stage A: S[16 x 32] = Q_w @ K^T
        float sf[4][4];
#pragma unroll
        for (int nt = 0; nt < 4; nt++)
#pragma unroll
            for (int r = 0; r < 4; r++) sf[nt][r] = 0.f;
#pragma unroll
        for (int kc = 0; kc < 64; kc += 8) {
            uint32_t af[4];
            ldsm4(af, aQaddr + (uint32_t)(kc * 4));
            uint32_t bk0[4], bk1[4];
            ldsm4(bk0, bKaddr + (uint32_t)(kc * 4));
            ldsm4(bk1, bKaddr + (uint32_t)((16 * 68 + kc) * 4));
            mma8(sf[0], af, bk0); mma8(sf[1], af, bk0 + 2);
            mma8(sf[2], af, bk1); mma8(sf[3], af, bk1 + 2);
        }

        // mask * exp, rowsum, stash S (tf32)
#pragma unroll
        for (int nt = 0; nt < 4; nt++) {
#pragma unroll
            for (int e = 0; e < 2; e++) {
                int lj = nt * 8 + t * 2 + e;
                int gj = j0 + lj;
                float cJ = scJ[lj], cJn = scJ[lj + 1];
                float d0 = (gj < gi0) ? (cI0 - cJ) : ((gj > gi0) ? (cJn - cI0n) : 0.f);
                float v0 = sf[nt][e] * __expf(d0);
                rs0 += v0;
                sS[iw + g][lj] = f2tf(v0);
                float d1 = (gj < gi1) ? (cI1 - cJ) : ((gj > gi1) ? (cJn - cI1n) : 0.f);
                float v1 = sf[nt][2 + e] * __expf(d1);
                rs1 += v1;
                sS[iw + g + 8][lj] = f2tf(v1);
            }
        }
        __syncthreads();

        // Stage B: O[16 x 64] += S[16 x 32] @ V[32 x 64]
#pragma unroll
        for (int kc = 0; kc < 32; kc += 8) {
            uint32_t af[4];
            ldsm4(af, aSaddr + (uint32_t)(kc * 4));
#pragma unroll
            for (int np = 0; np < 4; np++) {
                uint32_t bv[4];
                ldsm4(bv, bVaddr + (uint32_t)((np * 16 * 36 + kc) * 4));
                mma8(oacc[np * 2],     af, bv);
                mma8(oacc[np * 2 + 1], af, bv + 2);
            }
        }
    }

    rs0 += __shfl_xor_sync(~0u, rs0, 1);
    rs0 += __shfl_xor_sync(~0u, rs0, 2);
    rs1 += __shfl_xor_sync(~0u, rs1, 1);
    rs1 += __shfl_xor_sync(~0u, rs1, 2);
    float inv0 = 1.f / (rs0 + 1e-6f);
    float inv1 = 1.f / (rs1 + 1e-6f);

#pragma unroll
    for (int nt = 0; nt < 8; nt++) {
        int col = h * DD + nt * 8 + t * 2;
        float2 o0 = make_float2(oacc[nt][0] * inv0, oacc[nt][1] * inv0);
        float2 o1 = make_float2(oacc[nt][2] * inv1, oacc[nt][3] * inv1);
        *(float2*)(ctx + ((size_t)b * NN + gi0) * CC + col) = o0;
        *(float2*)(ctx + ((size_t)b * NN + gi1) * CC + col) = o1;
    }
}

// ---------------- launch ----------------
extern "C" void kernel_launch(void* const* d_in, const int* in_sizes, int n_in,
                              void* d_out, int out_size)
{
    (void)in_sizes; (void)n_in; (void)out_size;
    const float* x     = (const float*)d_in[0];
    const float* Wqkv  = (const float*)d_in[1];
    const float* Wa    = (const float*)d_in[2];
    const float* ba    = (const float*)d_in[3];
    const float* Wproj = (const float*)d_in[4];
    const float* bproj = (const float*)d_in[5];
    float* out = (float*)d_out;

    void *p_qkv, *p_q, *p_k, *p_loga, *p_c, *p_ctx;
    cudaGetSymbolAddress(&p_qkv, g_qkv);
    cudaGetSymbolAddress(&p_q, g_q);
    cudaGetSymbolAddress(&p_k, g_k);
    cudaGetSymbolAddress(&p_loga, g_loga);
    cudaGetSymbolAddress(&p_c, g_c);
    cudaGetSymbolAddress(&p_ctx, g_ctx);

    float* qkv  = (float*)p_qkv;
    float* q    = (float*)p_q;
    float* k    = (float*)p_k;
    float* loga = (float*)p_loga;
    float* cex  = (float*)p_c;
    float* ctx  = (float*)p_ctx;

    gemm_tf32<<<dim3(3 * CC / GBN, BB * NN / GBM), 256>>>(x, Wqkv, nullptr, qkv,
                                                          BB * NN, 3 * CC, CC);
    gate_kernel<<<BB * NN, 128>>>(x, Wa, ba, loga);
    scan_kernel<<<BB * HH, NN>>>(loga, cex);
    qknorm_kernel<<<dim3(BB * NN, 2), 384>>>(qkv, q, k);
    attn_tf32<<<dim3(BB * HH, NN / 64), 128>>>(q, k, qkv, cex, ctx);
    gemm_tf32<<<dim3(CC / GBN, BB * NN / GBM), 256>>>(ctx, Wproj, bproj, out,
                                                      BB * NN, CC, CC);
}

// round 4
// speedup vs baseline: 4.7690x; 1.0532x over previous
#include <cuda_runtime.h>
#include <cuda_bf16.h>
#include <cstdint>
#include <math.h>

#define BB 2
#define NN 1024
#define CC 768
#define HH 12
#define DD 64
#define SCALE 0.125f

// ---------------- scratch ----------------
__device__ float g_qkv[BB * NN * 3 * CC];
__device__ float g_q[BB * HH * NN * DD];
__device__ float g_k[BB * HH * NN * DD];
__device__ float g_loga[BB * HH * NN];
__device__ float g_c[BB * HH * (NN + 1)];
__device__ float g_ctx[BB * NN * CC];

// ---------------- tf32 helpers ----------------
__device__ __forceinline__ uint32_t f2tf(float x) {
    uint32_t r; asm("cvt.rna.tf32.f32 %0, %1;" : "=r"(r) : "f"(x)); return r;
}
__device__ __forceinline__ void mma8(float* d, const uint32_t* a, const uint32_t* b) {
    asm volatile(
        "mma.sync.aligned.m16n8k8.row.col.f32.tf32.tf32.f32 "
        "{%0,%1,%2,%3},{%4,%5,%6,%7},{%8,%9},{%0,%1,%2,%3};"
        : "+f"(d[0]), "+f"(d[1]), "+f"(d[2]), "+f"(d[3])
        : "r"(a[0]), "r"(a[1]), "r"(a[2]), "r"(a[3]), "r"(b[0]), "r"(b[1]));
}
__device__ __forceinline__ void ldsm4(uint32_t* r, uint32_t addr) {
    asm volatile("ldmatrix.sync.aligned.m8n8.x4.shared.b16 {%0,%1,%2,%3}, [%4];"
        : "=r"(r[0]), "=r"(r[1]), "=r"(r[2]), "=r"(r[3]) : "r"(addr));
}

// ---------------- tf32 GEMM, 2-stage double-buffered smem ----------------
#define GBM 128
#define GBN 128
#define GBK 16
#define GST 20
__global__ __launch_bounds__(256, 2) void gemm_tf32(
    const float* __restrict__ A, const float* __restrict__ W,
    const float* __restrict__ bias, float* __restrict__ C,
    int M, int N, int K)
{
    __shared__ uint32_t sA[2][GBM][GST];
    __shared__ uint32_t sB[2][GBN][GST];
    int tid = threadIdx.x;
    int lane = tid & 31, warp = tid >> 5;
    int g = lane >> 2, t = lane & 3;
    int wm = (warp & 1) * 64;
    int wn = (warp >> 1) * 32;
    int bm = blockIdx.y * GBM, bn = blockIdx.x * GBN;

    float acc[4][4][4];
#pragma unroll
    for (int i = 0; i < 4; i++)
#pragma unroll
        for (int j = 0; j < 4; j++)
#pragma unroll
            for (int r = 0; r < 4; r++) acc[i][j][r] = 0.f;

    int lr = tid >> 1;
    int lk = (tid & 1) * 8;
    const float* Ap = A + (size_t)(bm + lr) * K + lk;
    const float* Wp = W + (size_t)(bn + lr) * K + lk;

    uint32_t baseA = (uint32_t)__cvta_generic_to_shared(&sA[0][0][0]);
    uint32_t baseB = (uint32_t)__cvta_generic_to_shared(&sB[0][0][0]);
    const uint32_t bufA = GBM * GST * 4;
    const uint32_t bufB = GBN * GST * 4;
    int r8 = ((lane >> 3) & 1) * 8 + (lane & 7);
    int q4 = (lane >> 4) * 4;
    int rB = (lane >> 4) * 8 + (lane & 7);
    int cB4 = ((lane >> 3) & 1) * 4;
    uint32_t aaddr = baseA + (uint32_t)(((wm + r8) * GST + q4) * 4);
    uint32_t baddr = baseB + (uint32_t)(((wn + rB) * GST + cB4) * 4);

    int nk = K / GBK;
    float4 ra0 = *(const float4*)(Ap);
    float4 ra1 = *(const float4*)(Ap + 4);
    float4 rb0 = *(const float4*)(Wp);
    float4 rb1 = *(const float4*)(Wp + 4);

    // store chunk 0 into buf 0
    *(uint4*)&sA[0][lr][lk]     = make_uint4(f2tf(ra0.x), f2tf(ra0.y), f2tf(ra0.z), f2tf(ra0.w));
    *(uint4*)&sA[0][lr][lk + 4] = make_uint4(f2tf(ra1.x), f2tf(ra1.y), f2tf(ra1.z), f2tf(ra1.w));
    *(uint4*)&sB[0][lr][lk]     = make_uint4(f2tf(rb0.x), f2tf(rb0.y), f2tf(rb0.z), f2tf(rb0.w));
    *(uint4*)&sB[0][lr][lk + 4] = make_uint4(f2tf(rb1.x), f2tf(rb1.y), f2tf(rb1.z), f2tf(rb1.w));
    // prefetch chunk 1
    ra0 = *(const float4*)(Ap + GBK);
    ra1 = *(const float4*)(Ap + GBK + 4);
    rb0 = *(const float4*)(Wp + GBK);
    rb1 = *(const float4*)(Wp + GBK + 4);
    __syncthreads();

    for (int i = 0; i < nk; i++) {
        int cur = i & 1;
        // store chunk i+1 into the other buffer (overlaps compute)
        if (i + 1 < nk) {
            int nxt = cur ^ 1;
            *(uint4*)&sA[nxt][lr][lk]     = make_uint4(f2tf(ra0.x), f2tf(ra0.y), f2tf(ra0.z), f2tf(ra0.w));
            *(uint4*)&sA[nxt][lr][lk + 4] = make_uint4(f2tf(ra1.x), f2tf(ra1.y), f2tf(ra1.z), f2tf(ra1.w));
            *(uint4*)&sB[nxt][lr][lk]     = make_uint4(f2tf(rb0.x), f2tf(rb0.y), f2tf(rb0.z), f2tf(rb0.w));
            *(uint4*)&sB[nxt][lr][lk + 4] = make_uint4(f2tf(rb1.x), f2tf(rb1.y), f2tf(rb1.z), f2tf(rb1.w));
        }
        // issue gmem loads for chunk i+2
        if (i + 2 < nk) {
            int k2 = (i + 2) * GBK;
            ra0 = *(const float4*)(Ap + k2);
            ra1 = *(const float4*)(Ap + k2 + 4);
            rb0 = *(const float4*)(Wp + k2);
            rb1 = *(const float4*)(Wp + k2 + 4);
        }
        uint32_t aoff = cur * bufA, boff = cur * bufB;
#pragma unroll
        for (int kc = 0; kc < GBK; kc += 8) {
            uint32_t af[4][4];
#pragma unroll
            for (int mt = 0; mt < 4; mt++)
                ldsm4(af[mt], aaddr + aoff + (uint32_t)((mt * 16 * GST + kc) * 4));
            uint32_t bf[2][4];
#pragma unroll
            for (int p = 0; p < 2; p++)
                ldsm4(bf[p], baddr + boff + (uint32_t)((p * 16 * GST + kc) * 4));
#pragma unroll
            for (int mt = 0; mt < 4; mt++) {
                mma8(acc[mt][0], af[mt], bf[0]);
                mma8(acc[mt][1], af[mt], bf[0] + 2);
                mma8(acc[mt][2], af[mt], bf[1]);
                mma8(acc[mt][3], af[mt], bf[1] + 2);
            }
        }
        __syncthreads();
    }

#pragma unroll
    for (int mt = 0; mt < 4; mt++) {
#pragma unroll
        for (int nt = 0; nt < 4; nt++) {
            int row = bm + wm + mt * 16 + g;
            int col = bn + wn + nt * 8 + t * 2;
            float b0 = bias ? bias[col] : 0.f;
            float b1 = bias ? bias[col + 1] : 0.f;
            float2 o0 = make_float2(acc[mt][nt][0] + b0, acc[mt][nt][1] + b1);
            float2 o1 = make_float2(acc[mt][nt][2] + b0, acc[mt][nt][3] + b1);
            *(float2*)(C + (size_t)row * N + col) = o0;
            *(float2*)(C + (size_t)(row + 8) * N + col) = o1;
        }
    }
}

// ---------------- fused prep: gate + q/k silu-norm (warp per head) ----------------
__global__ __launch_bounds__(384) void prep_kernel(
    const float* __restrict__ x, const float* __restrict__ Wa,
    const float* __restrict__ ba, const float* __restrict__ qkv,
    float* __restrict__ Qn, float* __restrict__ Kn, float* __restrict__ loga)
{
    int bn = blockIdx.x;
    int b = bn >> 10, n = bn & 1023;
    int tid = threadIdx.x;
    int h = tid >> 5, lane = tid & 31;
    __shared__ float sx[CC];
    if (tid < CC / 4)
        *(float4*)&sx[tid * 4] = *(const float4*)(x + (size_t)bn * CC + tid * 4);
    __syncthreads();

    // gate logit for head h
    float p = 0.f;
#pragma unroll
    for (int c = 0; c < CC / 32; c++) p = fmaf(sx[lane + c * 32], Wa[h * CC + lane + c * 32], p);
#pragma unroll
    for (int o = 16; o; o >>= 1) p += __shfl_xor_sync(~0u, p, o);
    if (lane == 0) {
        float z = p + ba[h];
        float la = -(fmaxf(z, 0.f) + log1pf(__expf(-fabsf(z))));
        loga[((size_t)b * HH + h) * NN + n] = (n == 0) ? 0.f : la;
    }

    // q/k norm for head h
#pragma unroll
    for (int s = 0; s < 2; s++) {
        const float* src = qkv + (size_t)bn * (3 * CC) + s * CC + h * DD;
        float z0 = src[lane], z1 = src[lane + 32];
        float r0 = z0 / (1.f + __expf(-z0)) + 0.5f;
        float r1 = z1 / (1.f + __expf(-z1)) + 0.5f;
        float q = r0 * r0 + r1 * r1;
#pragma unroll
        for (int o = 16; o; o >>= 1) q += __shfl_xor_sync(~0u, q, o);
        float inv = rsqrtf(q);
        float* dst = (s ? Kn : Qn) + (((size_t)b * HH + h) * NN + (size_t)n) * DD;
        dst[lane] = r0 * inv;
        dst[lane + 32] = r1 * inv;
    }
}

// ---------------- scan ----------------
__global__ void scan_kernel(const float* __restrict__ loga, float* __restrict__ Cex)
{
    int bh = blockIdx.x;
    int t = threadIdx.x, lane = t & 31, w = t >> 5;
    __shared__ float wsum[32];
    float s = loga[(size_t)bh * NN + t];
#pragma unroll
    for (int o = 1; o < 32; o <<= 1) {
        float u = __shfl_up_sync(~0u, s, o);
        if (lane >= o) s += u;
    }
    if (lane == 31) wsum[w] = s;
    __syncthreads();
    if (w == 0) {
        float ws = wsum[lane];
#pragma unroll
        for (int o = 1; o < 32; o <<= 1) {
            float u = __shfl_up_sync(~0u, ws, o);
            if (lane >= o) ws += u;
        }
        wsum[lane] = ws;
    }
    __syncthreads();
    float base = w ? wsum[w - 1] : 0.f;
    Cex[(size_t)bh * (NN + 1) + t + 1] = s + base;
    if (t == 0) Cex[(size_t)bh * (NN + 1)] = 0.f;
}

// ---------------- fused attention, j-tile 64 ----------------
#define AST 68
__global__ __launch_bounds__(128) void attn_tf32(
    const float* __restrict__ Q, const float* __restrict__ Kt,
    const float* __restrict__ qkv, const float* __restrict__ Cex,
    float* __restrict__ ctx)
{
    int bh = blockIdx.x;
    int i0 = blockIdx.y * 64;
    int b = bh / HH, h = bh % HH;

    __shared__ uint32_t sQ[64][AST];   // [i][d]
    __shared__ uint32_t sK[64][AST];   // [j][d]
    __shared__ uint32_t sVt[64][AST];  // [d][j]
    __shared__ uint32_t sS[64][AST];   // [i][j]
    __shared__ float scI[65];
    __shared__ float scJ[65];

    int tid = threadIdx.x;
    int lane = tid & 31, warp = tid >> 5;
    int g = lane >> 2, t = lane & 3;
    int iw = warp * 16;

    uint32_t baseQ = (uint32_t)__cvta_generic_to_shared(&sQ[0][0]);
    uint32_t baseK = (uint32_t)__cvta_generic_to_shared(&sK[0][0]);
    uint32_t baseV = (uint32_t)__cvta_generic_to_shared(&sVt[0][0]);
    uint32_t baseS = (uint32_t)__cvta_generic_to_shared(&sS[0][0]);
    int r8 = ((lane >> 3) & 1) * 8 + (lane & 7);
    int q4 = (lane >> 4) * 4;
    int rB = (lane >> 4) * 8 + (lane & 7);
    int cB4 = ((lane >> 3) & 1) * 4;
    uint32_t aQaddr = baseQ + (uint32_t)(((iw + r8) * AST + q4) * 4);
    uint32_t aSaddr = baseS + (uint32_t)(((iw + r8) * AST + q4) * 4);
    uint32_t bKaddr = baseK + (uint32_t)((rB * AST + cB4) * 4);
    uint32_t bVaddr = baseV + (uint32_t)((rB * AST + cB4) * 4);

    // Q tile (pre-scaled)
#pragma unroll
    for (int l = 0; l < 8; l++) {
        int f = tid + l * 128;
        int i = f >> 4, d4 = (f & 15) * 4;
        float4 v = *(const float4*)(Q + (((size_t)bh * NN) + i0 + i) * DD + d4);
        *(uint4*)&sQ[i][d4] = make_uint4(f2tf(v.x * SCALE), f2tf(v.y * SCALE),
                                         f2tf(v.z * SCALE), f2tf(v.w * SCALE));
    }
    if (tid < 65) scI[tid] = Cex[(size_t)bh * (NN + 1) + i0 + tid];

    float oacc[8][4];
#pragma unroll
    for (int nt = 0; nt < 8; nt++)
#pragma unroll
        for (int r = 0; r < 4; r++) oacc[nt][r] = 0.f;
    float rs0 = 0.f, rs1 = 0.f;

    const float* vbase = qkv + (size_t)b * NN * (3 * CC) + 2 * CC + h * DD;

    float cI0 = 0.f, cI0n = 0.f, cI1 = 0.f, cI1n = 0.f;
    int gi0 = i0 + iw + g, gi1 = gi0 + 8;

    int dv = (warp & 1) * 32 + lane;   // owned d column for V transpose
    int qv = warp >> 1;                // j-group (0..1), each 32 j's

    for (int j0 = 0; j0 < NN; j0 += 64) {
        __syncthreads();
        // K tile [j][d]
#pragma unroll
        for (int l = 0; l < 8; l++) {
            int f = tid + l * 128;
            int j = f >> 4, d4 = (f & 15) * 4;
            float4 kv = *(const float4*)(Kt + (((size_t)bh * NN) + j0 + j) * DD + d4);
            *(uint4*)&sK[j][d4] = make_uint4(f2tf(kv.x), f2tf(kv.y), f2tf(kv.z), f2tf(kv.w));
        }
        // V transposed [d][j]: lane owns column dv, STS.128 along j (conflict-free)
#pragma unroll
        for (int l = 0; l < 8; l++) {
            int j4 = (qv * 8 + l) * 4;
            const float* vp = vbase + (size_t)(j0 + j4) * (3 * CC) + dv;
            uint32_t w0 = f2tf(vp[0]);
            uint32_t w1 = f2tf(vp[3 * CC]);
            uint32_t w2 = f2tf(vp[6 * CC]);
            uint32_t w3 = f2tf(vp[9 * CC]);
            *(uint4*)&sVt[dv][j4] = make_uint4(w0, w1, w2, w3);
        }
        if (tid < 65) scJ[tid] = Cex[(size_t)bh * (NN + 1) + j0 + tid];
        if (j0 == 0) {
            cI0 = scI[iw + g];     cI0n = scI[iw + g + 1];
            cI1 = scI[iw + g + 8]; cI1n = scI[iw + g + 9];
        }
        __syncthreads();

        // Stage A: S[16 x 64]
        float sf[8][4];
#pragma unroll
        for (int nt = 0; nt < 8; nt++)
#pragma unroll
            for (int r = 0; r < 4; r++) sf[nt][r] = 0.f;
#pragma unroll
        for (int kc = 0; kc < 64; kc += 8) {
            uint32_t af[4];
            ldsm4(af, aQaddr + (uint32_t)(kc * 4));
#pragma unroll
            for (int np = 0; np < 4; np++) {
                uint32_t bk[4];
                ldsm4(bk, bKaddr + (uint32_t)((np * 16 * AST + kc) * 4));
                mma8(sf[np * 2], af, bk);
                mma8(sf[np * 2 + 1], af, bk + 2);
            }
        }

        // mask * exp, rowsum, stash S
#pragma unroll
        for (int nt = 0; nt < 8; nt++) {
#pragma unroll
            for (int e = 0; e < 2; e++) {
                int lj = nt * 8 + t * 2 + e;
                int gj = j0 + lj;
                float cJ = scJ[lj], cJn = scJ[lj + 1];
                float d0 = (gj < gi0) ? (cI0 - cJ) : ((gj > gi0) ? (cJn - cI0n) : 0.f);
                float v0 = sf[nt][e] * __expf(d0);
                rs0 += v0;
                sS[iw + g][lj] = f2tf(v0);
                float d1 = (gj < gi1) ? (cI1 - cJ) : ((gj > gi1) ? (cJn - cI1n) : 0.f);
                float v1 = sf[nt][2 + e] * __expf(d1);
                rs1 += v1;
                sS[iw + g + 8][lj] = f2tf(v1);
            }
        }
        __syncthreads();

        // Stage B: O[16 x 64] += S[16 x 64] @ V[64 x 64]
#pragma unroll
        for (int kc = 0; kc < 64; kc += 8) {
            uint32_t af[4];
            ldsm4(af, aSaddr + (uint32_t)(kc * 4));
#pragma unroll
            for (int np = 0; np < 4; np++) {
                uint32_t bv[4];
                ldsm4(bv, bVaddr + (uint32_t)((np * 16 * AST + kc) * 4));
                mma8(oacc[np * 2],     af, bv);
                mma8(oacc[np * 2 + 1], af, bv + 2);
            }
        }
    }

    rs0 += __shfl_xor_sync(~0u, rs0, 1);
    rs0 += __shfl_xor_sync(~0u, rs0, 2);
    rs1 += __shfl_xor_sync(~0u, rs1, 1);
    rs1 += __shfl_xor_sync(~0u, rs1, 2);
    float inv0 = 1.f / (rs0 + 1e-6f);
    float inv1 = 1.f / (rs1 + 1e-6f);

#pragma unroll
    for (int nt = 0; nt < 8; nt++) {
        int col = h * DD + nt * 8 + t * 2;
        float2 o0 = make_float2(oacc[nt][0] * inv0, oacc[nt][1] * inv0);
        float2 o1 = make_float2(oacc[nt][2] * inv1, oacc[nt][3] * inv1);
        *(float2*)(ctx + ((size_t)b * NN + gi0) * CC + col) = o0;
        *(float2*)(ctx + ((size_t)b * NN + gi1) * CC + col) = o1;
    }
}

// ---------------- launch ----------------
extern "C" void kernel_launch(void* const* d_in, const int* in_sizes, int n_in,
                              void* d_out, int out_size)
{
    (void)in_sizes; (void)n_in; (void)out_size;
    const float* x     = (const float*)d_in[0];
    const float* Wqkv  = (const float*)d_in[1];
    const float* Wa    = (const float*)d_in[2];
    const float* ba    = (const float*)d_in[3];
    const float* Wproj = (const float*)d_in[4];
    const float* bproj = (const float*)d_in[5];
    float* out = (float*)d_out;

    void *p_qkv, *p_q, *p_k, *p_loga, *p_c, *p_ctx;
    cudaGetSymbolAddress(&p_qkv, g_qkv);
    cudaGetSymbolAddress(&p_q, g_q);
    cudaGetSymbolAddress(&p_k, g_k);
    cudaGetSymbolAddress(&p_loga, g_loga);
    cudaGetSymbolAddress(&p_c, g_c);
    cudaGetSymbolAddress(&p_ctx, g_ctx);

    float* qkv  = (float*)p_qkv;
    float* q    = (float*)p_q;
    float* k    = (float*)p_k;
    float* loga = (float*)p_loga;
    float* cex  = (float*)p_c;
    float* ctx  = (float*)p_ctx;

    gemm_tf32<<<dim3(3 * CC / GBN, BB * NN / GBM), 256>>>(x, Wqkv, nullptr, qkv,
                                                          BB * NN, 3 * CC, CC);
    prep_kernel<<<BB * NN, 384>>>(x, Wa, ba, qkv, q, k, loga);
    scan_kernel<<<BB * HH, NN>>>(loga, cex);
    attn_tf32<<<dim3(BB * HH, NN / 64), 128>>>(q, k, qkv, cex, ctx);
    gemm_tf32<<<dim3(CC / GBN, BB * NN / GBM), 256>>>(ctx, Wproj, bproj, out,
                                                      BB * NN, CC, CC);
}

// round 5
// speedup vs baseline: 4.8039x; 1.0073x over previous
#include <cuda_runtime.h>
#include <cuda_bf16.h>
#include <cstdint>
#include <math.h>

#define BB 2
#define NN 1024
#define CC 768
#define HH 12
#define DD 64
#define SCALE 0.125f

// ---------------- scratch ----------------
__device__ float g_qkv[BB * NN * 3 * CC];
__device__ float g_q[BB * HH * NN * DD];
__device__ float g_k[BB * HH * NN * DD];
__device__ float g_loga[BB * HH * NN];
__device__ float g_c[BB * HH * (NN + 1)];
__device__ float g_ctx[BB * NN * CC];

// ---------------- tf32 helpers ----------------
__device__ __forceinline__ uint32_t f2tf(float x) {
    uint32_t r; asm("cvt.rna.tf32.f32 %0, %1;" : "=r"(r) : "f"(x)); return r;
}
__device__ __forceinline__ void mma8(float* d, const uint32_t* a, const uint32_t* b) {
    asm volatile(
        "mma.sync.aligned.m16n8k8.row.col.f32.tf32.tf32.f32 "
        "{%0,%1,%2,%3},{%4,%5,%6,%7},{%8,%9},{%0,%1,%2,%3};"
        : "+f"(d[0]), "+f"(d[1]), "+f"(d[2]), "+f"(d[3])
        : "r"(a[0]), "r"(a[1]), "r"(a[2]), "r"(a[3]), "r"(b[0]), "r"(b[1]));
}
__device__ __forceinline__ void ldsm4(uint32_t* r, uint32_t addr) {
    asm volatile("ldmatrix.sync.aligned.m8n8.x4.shared.b16 {%0,%1,%2,%3}, [%4];"
        : "=r"(r[0]), "=r"(r[1]), "=r"(r[2]), "=r"(r[3]) : "r"(addr));
}

// ---------------- tf32 GEMM, 2-stage double-buffered smem ----------------
#define GBM 128
#define GBN 128
#define GBK 16
#define GST 20
__global__ __launch_bounds__(256, 2) void gemm_tf32(
    const float* __restrict__ A, const float* __restrict__ W,
    const float* __restrict__ bias, float* __restrict__ C,
    int M, int N, int K)
{
    __shared__ uint32_t sA[2][GBM][GST];
    __shared__ uint32_t sB[2][GBN][GST];
    int tid = threadIdx.x;
    int lane = tid & 31, warp = tid >> 5;
    int g = lane >> 2, t = lane & 3;
    int wm = (warp & 1) * 64;
    int wn = (warp >> 1) * 32;
    int bm = blockIdx.y * GBM, bn = blockIdx.x * GBN;

    float acc[4][4][4];
#pragma unroll
    for (int i = 0; i < 4; i++)
#pragma unroll
        for (int j = 0; j < 4; j++)
#pragma unroll
            for (int r = 0; r < 4; r++) acc[i][j][r] = 0.f;

    int lr = tid >> 1;
    int lk = (tid & 1) * 8;
    const float* Ap = A + (size_t)(bm + lr) * K + lk;
    const float* Wp = W + (size_t)(bn + lr) * K + lk;

    uint32_t baseA = (uint32_t)__cvta_generic_to_shared(&sA[0][0][0]);
    uint32_t baseB = (uint32_t)__cvta_generic_to_shared(&sB[0][0][0]);
    const uint32_t bufA = GBM * GST * 4;
    const uint32_t bufB = GBN * GST * 4;
    int r8 = ((lane >> 3) & 1) * 8 + (lane & 7);
    int q4 = (lane >> 4) * 4;
    int rB = (lane >> 4) * 8 + (lane & 7);
    int cB4 = ((lane >> 3) & 1) * 4;
    uint32_t aaddr = baseA + (uint32_t)(((wm + r8) * GST + q4) * 4);
    uint32_t baddr = baseB + (uint32_t)(((wn + rB) * GST + cB4) * 4);

    int nk = K / GBK;
    float4 ra0 = *(const float4*)(Ap);
    float4 ra1 = *(const float4*)(Ap + 4);
    float4 rb0 = *(const float4*)(Wp);
    float4 rb1 = *(const float4*)(Wp + 4);

    *(uint4*)&sA[0][lr][lk]     = make_uint4(f2tf(ra0.x), f2tf(ra0.y), f2tf(ra0.z), f2tf(ra0.w));
    *(uint4*)&sA[0][lr][lk + 4] = make_uint4(f2tf(ra1.x), f2tf(ra1.y), f2tf(ra1.z), f2tf(ra1.w));
    *(uint4*)&sB[0][lr][lk]     = make_uint4(f2tf(rb0.x), f2tf(rb0.y), f2tf(rb0.z), f2tf(rb0.w));
    *(uint4*)&sB[0][lr][lk + 4] = make_uint4(f2tf(rb1.x), f2tf(rb1.y), f2tf(rb1.z), f2tf(rb1.w));
    ra0 = *(const float4*)(Ap + GBK);
    ra1 = *(const float4*)(Ap + GBK + 4);
    rb0 = *(const float4*)(Wp + GBK);
    rb1 = *(const float4*)(Wp + GBK + 4);
    __syncthreads();

    for (int i = 0; i < nk; i++) {
        int cur = i & 1;
        if (i + 1 < nk) {
            int nxt = cur ^ 1;
            *(uint4*)&sA[nxt][lr][lk]     = make_uint4(f2tf(ra0.x), f2tf(ra0.y), f2tf(ra0.z), f2tf(ra0.w));
            *(uint4*)&sA[nxt][lr][lk + 4] = make_uint4(f2tf(ra1.x), f2tf(ra1.y), f2tf(ra1.z), f2tf(ra1.w));
            *(uint4*)&sB[nxt][lr][lk]     = make_uint4(f2tf(rb0.x), f2tf(rb0.y), f2tf(rb0.z), f2tf(rb0.w));
            *(uint4*)&sB[nxt][lr][lk + 4] = make_uint4(f2tf(rb1.x), f2tf(rb1.y), f2tf(rb1.z), f2tf(rb1.w));
        }
        if (i + 2 < nk) {
            int k2 = (i + 2) * GBK;
            ra0 = *(const float4*)(Ap + k2);
            ra1 = *(const float4*)(Ap + k2 + 4);
            rb0 = *(const float4*)(Wp + k2);
            rb1 = *(const float4*)(Wp + k2 + 4);
        }
        uint32_t aoff = cur * bufA, boff = cur * bufB;
#pragma unroll
        for (int kc = 0; kc < GBK; kc += 8) {
            uint32_t af[4][4];
#pragma unroll
            for (int mt = 0; mt < 4; mt++)
                ldsm4(af[mt], aaddr + aoff + (uint32_t)((mt * 16 * GST + kc) * 4));
            uint32_t bf[2][4];
#pragma unroll
            for (int p = 0; p < 2; p++)
                ldsm4(bf[p], baddr + boff + (uint32_t)((p * 16 * GST + kc) * 4));
#pragma unroll
            for (int mt = 0; mt < 4; mt++) {
                mma8(acc[mt][0], af[mt], bf[0]);
                mma8(acc[mt][1], af[mt], bf[0] + 2);
                mma8(acc[mt][2], af[mt], bf[1]);
                mma8(acc[mt][3], af[mt], bf[1] + 2);
            }
        }
        __syncthreads();
    }

#pragma unroll
    for (int mt = 0; mt < 4; mt++) {
#pragma unroll
        for (int nt = 0; nt < 4; nt++) {
            int row = bm + wm + mt * 16 + g;
            int col = bn + wn + nt * 8 + t * 2;
            float b0 = bias ? bias[col] : 0.f;
            float b1 = bias ? bias[col + 1] : 0.f;
            float2 o0 = make_float2(acc[mt][nt][0] + b0, acc[mt][nt][1] + b1);
            float2 o1 = make_float2(acc[mt][nt][2] + b0, acc[mt][nt][3] + b1);
            *(float2*)(C + (size_t)row * N + col) = o0;
            *(float2*)(C + (size_t)(row + 8) * N + col) = o1;
        }
    }
}

// ---------------- fused prep: gate + q/k silu-norm (warp per head) ----------------
__global__ __launch_bounds__(384) void prep_kernel(
    const float* __restrict__ x, const float* __restrict__ Wa,
    const float* __restrict__ ba, const float* __restrict__ qkv,
    float* __restrict__ Qn, float* __restrict__ Kn, float* __restrict__ loga)
{
    int bn = blockIdx.x;
    int b = bn >> 10, n = bn & 1023;
    int tid = threadIdx.x;
    int h = tid >> 5, lane = tid & 31;
    __shared__ float sx[CC];
    if (tid < CC / 4)
        *(float4*)&sx[tid * 4] = *(const float4*)(x + (size_t)bn * CC + tid * 4);
    __syncthreads();

    float p = 0.f;
#pragma unroll
    for (int c = 0; c < CC / 32; c++) p = fmaf(sx[lane + c * 32], Wa[h * CC + lane + c * 32], p);
#pragma unroll
    for (int o = 16; o; o >>= 1) p += __shfl_xor_sync(~0u, p, o);
    if (lane == 0) {
        float z = p + ba[h];
        float la = -(fmaxf(z, 0.f) + log1pf(__expf(-fabsf(z))));
        loga[((size_t)b * HH + h) * NN + n] = (n == 0) ? 0.f : la;
    }

#pragma unroll
    for (int s = 0; s < 2; s++) {
        const float* src = qkv + (size_t)bn * (3 * CC) + s * CC + h * DD;
        float z0 = src[lane], z1 = src[lane + 32];
        float r0 = z0 / (1.f + __expf(-z0)) + 0.5f;
        float r1 = z1 / (1.f + __expf(-z1)) + 0.5f;
        float q = r0 * r0 + r1 * r1;
#pragma unroll
        for (int o = 16; o; o >>= 1) q += __shfl_xor_sync(~0u, q, o);
        float inv = rsqrtf(q);
        float* dst = (s ? Kn : Qn) + (((size_t)b * HH + h) * NN + (size_t)n) * DD;
        dst[lane] = r0 * inv;
        dst[lane + 32] = r1 * inv;
    }
}

// ---------------- scan ----------------
__global__ void scan_kernel(const float* __restrict__ loga, float* __restrict__ Cex)
{
    int bh = blockIdx.x;
    int t = threadIdx.x, lane = t & 31, w = t >> 5;
    __shared__ float wsum[32];
    float s = loga[(size_t)bh * NN + t];
#pragma unroll
    for (int o = 1; o < 32; o <<= 1) {
        float u = __shfl_up_sync(~0u, s, o);
        if (lane >= o) s += u;
    }
    if (lane == 31) wsum[w] = s;
    __syncthreads();
    if (w == 0) {
        float ws = wsum[lane];
#pragma unroll
        for (int o = 1; o < 32; o <<= 1) {
            float u = __shfl_up_sync(~0u, ws, o);
            if (lane >= o) ws += u;
        }
        wsum[lane] = ws;
    }
    __syncthreads();
    float base = w ? wsum[w - 1] : 0.f;
    Cex[(size_t)bh * (NN + 1) + t + 1] = s + base;
    if (t == 0) Cex[(size_t)bh * (NN + 1)] = 0.f;
}

// ---------------- fused attention: 8 warps, j-split warpgroups ----------------
#define AST 68
__global__ __launch_bounds__(256) void attn_tf32(
    const float* __restrict__ Q, const float* __restrict__ Kt,
    const float* __restrict__ qkv, const float* __restrict__ Cex,
    float* __restrict__ ctx)
{
    int bh = blockIdx.x;
    int i0 = blockIdx.y * 64;
    int b = bh / HH, h = bh % HH;

    __shared__ uint32_t sQ[64][AST];   // [i][d]
    __shared__ uint32_t sK[64][AST];   // [j][d]
    __shared__ uint32_t sVt[64][AST];  // [d][j]
    __shared__ uint32_t sS[64][AST];   // [i][j]; reused as float scratch at end
    __shared__ float scI[65];
    __shared__ float scJ[65];
    __shared__ float srs[64];

    int tid = threadIdx.x;
    int lane = tid & 31, warp = tid >> 5;
    int g = lane >> 2, t = lane & 3;
    int wi = warp & 3;          // i-subtile 0..3
    int wg = warp >> 2;         // j-half 0..1
    int iw = wi * 16;
    int jh = wg * 32;

    uint32_t baseQ = (uint32_t)__cvta_generic_to_shared(&sQ[0][0]);
    uint32_t baseK = (uint32_t)__cvta_generic_to_shared(&sK[0][0]);
    uint32_t baseV = (uint32_t)__cvta_generic_to_shared(&sVt[0][0]);
    uint32_t baseS = (uint32_t)__cvta_generic_to_shared(&sS[0][0]);
    int r8 = ((lane >> 3) & 1) * 8 + (lane & 7);
    int q4 = (lane >> 4) * 4;
    int rB = (lane >> 4) * 8 + (lane & 7);
    int cB4 = ((lane >> 3) & 1) * 4;
    uint32_t aQaddr = baseQ + (uint32_t)(((iw + r8) * AST + q4) * 4);
    uint32_t aSaddr = baseS + (uint32_t)(((iw + r8) * AST + q4) * 4);
    uint32_t bKaddr = baseK + (uint32_t)(((jh + rB) * AST + cB4) * 4);
    uint32_t bVaddr = baseV + (uint32_t)((rB * AST + cB4) * 4);

    // Q tile (pre-scaled)
#pragma unroll
    for (int l = 0; l < 4; l++) {
        int f = tid + l * 256;
        int i = f >> 4, d4 = (f & 15) * 4;
        float4 v = *(const float4*)(Q + (((size_t)bh * NN) + i0 + i) * DD + d4);
        *(uint4*)&sQ[i][d4] = make_uint4(f2tf(v.x * SCALE), f2tf(v.y * SCALE),
                                         f2tf(v.z * SCALE), f2tf(v.w * SCALE));
    }
    if (tid < 65) scI[tid] = Cex[(size_t)bh * (NN + 1) + i0 + tid];

    float oacc[8][4];
#pragma unroll
    for (int nt = 0; nt < 8; nt++)
#pragma unroll
        for (int r = 0; r < 4; r++) oacc[nt][r] = 0.f;
    float rs0 = 0.f, rs1 = 0.f;

    const float* vbase = qkv + (size_t)b * NN * (3 * CC) + 2 * CC + h * DD;

    float cI0 = 0.f, cI0n = 0.f, cI1 = 0.f, cI1n = 0.f;
    int gi0 = i0 + iw + g, gi1 = gi0 + 8;

    int dv = (warp & 1) * 32 + lane;     // owned d column for V transpose
    int qv = (warp >> 1) & 3;            // j-quarter (16 j's)

    for (int j0 = 0; j0 < NN; j0 += 64) {
        __syncthreads();
        // K tile [j][d]
#pragma unroll
        for (int l = 0; l < 4; l++) {
            int f = tid + l * 256;
            int j = f >> 4, d4 = (f & 15) * 4;
            float4 kv = *(const float4*)(Kt + (((size_t)bh * NN) + j0 + j) * DD + d4);
            *(uint4*)&sK[j][d4] = make_uint4(f2tf(kv.x), f2tf(kv.y), f2tf(kv.z), f2tf(kv.w));
        }
        // V transposed [d][j], STS.128 along j (conflict-free)
#pragma unroll
        for (int l = 0; l < 4; l++) {
            int j4 = (qv * 4 + l) * 4;
            const float* vp = vbase + (size_t)(j0 + j4) * (3 * CC) + dv;
            uint32_t w0 = f2tf(vp[0]);
            uint32_t w1 = f2tf(vp[3 * CC]);
            uint32_t w2 = f2tf(vp[6 * CC]);
            uint32_t w3 = f2tf(vp[9 * CC]);
            *(uint4*)&sVt[dv][j4] = make_uint4(w0, w1, w2, w3);
        }
        if (tid < 65) scJ[tid] = Cex[(size_t)bh * (NN + 1) + j0 + tid];
        if (j0 == 0) {
            cI0 = scI[iw + g];     cI0n = scI[iw + g + 1];
            cI1 = scI[iw + g + 8]; cI1n = scI[iw + g + 9];
        }
        __syncthreads();

        // Stage A: S[16 x 32] over this warp's j-half
        float sf[4][4];
#pragma unroll
        for (int nt = 0; nt < 4; nt++)
#pragma unroll
            for (int r = 0; r < 4; r++) sf[nt][r] = 0.f;
#pragma unroll
        for (int kc = 0; kc < 64; kc += 8) {
            uint32_t af[4];
            ldsm4(af, aQaddr + (uint32_t)(kc * 4));
#pragma unroll
            for (int np = 0; np < 2; np++) {
                uint32_t bk[4];
                ldsm4(bk, bKaddr + (uint32_t)((np * 16 * AST + kc) * 4));
                mma8(sf[np * 2], af, bk);
                mma8(sf[np * 2 + 1], af, bk + 2);
            }
        }

        // mask * exp, rowsum, stash S
#pragma unroll
        for (int nt = 0; nt < 4; nt++) {
#pragma unroll
            for (int e = 0; e < 2; e++) {
                int lj = jh + nt * 8 + t * 2 + e;
                int gj = j0 + lj;
                float cJ = scJ[lj], cJn = scJ[lj + 1];
                float d0 = (gj < gi0) ? (cI0 - cJ) : ((gj > gi0) ? (cJn - cI0n) : 0.f);
                float v0 = sf[nt][e] * __expf(d0);
                rs0 += v0;
                sS[iw + g][lj] = f2tf(v0);
                float d1 = (gj < gi1) ? (cI1 - cJ) : ((gj > gi1) ? (cJn - cI1n) : 0.f);
                float v1 = sf[nt][2 + e] * __expf(d1);
                rs1 += v1;
                sS[iw + g + 8][lj] = f2tf(v1);
            }
        }
        __syncthreads();

        // Stage B: O[16 x 64] += S[16 x 32] @ V[32 x 64] (own j-half)
#pragma unroll
        for (int kk = 0; kk < 32; kk += 8) {
            int kc = jh + kk;
            uint32_t af[4];
            ldsm4(af, aSaddr + (uint32_t)(kc * 4));
#pragma unroll
            for (int np = 0; np < 4; np++) {
                uint32_t bv[4];
                ldsm4(bv, bVaddr + (uint32_t)((np * 16 * AST + kc) * 4));
                mma8(oacc[np * 2],     af, bv);
                mma8(oacc[np * 2 + 1], af, bv + 2);
            }
        }
    }

    // reduce rowsums within lane quads
    rs0 += __shfl_xor_sync(~0u, rs0, 1);
    rs0 += __shfl_xor_sync(~0u, rs0, 2);
    rs1 += __shfl_xor_sync(~0u, rs1, 1);
    rs1 += __shfl_xor_sync(~0u, rs1, 2);

    // combine the two warpgroups' partial O and rowsums via smem
    __syncthreads();                    // stage-B reads of sS done
    float* scratch = (float*)&sS[0][0]; // reuse as [64][AST] float
    if (wg == 1) {
#pragma unroll
        for (int nt = 0; nt < 8; nt++) {
            int col = nt * 8 + t * 2;
            scratch[(iw + g) * AST + col]     = oacc[nt][0];
            scratch[(iw + g) * AST + col + 1] = oacc[nt][1];
            scratch[(iw + g + 8) * AST + col]     = oacc[nt][2];
            scratch[(iw + g + 8) * AST + col + 1] = oacc[nt][3];
        }
        if (t == 0) { srs[iw + g] = rs0; srs[iw + g + 8] = rs1; }
    }
    __syncthreads();
    if (wg == 0) {
        float inv0 = 1.f / (rs0 + srs[iw + g] + 1e-6f);
        float inv1 = 1.f / (rs1 + srs[iw + g + 8] + 1e-6f);
#pragma unroll
        for (int nt = 0; nt < 8; nt++) {
            int col = nt * 8 + t * 2;
            float2 o0, o1;
            o0.x = (oacc[nt][0] + scratch[(iw + g) * AST + col])     * inv0;
            o0.y = (oacc[nt][1] + scratch[(iw + g) * AST + col + 1]) * inv0;
            o1.x = (oacc[nt][2] + scratch[(iw + g + 8) * AST + col])     * inv1;
            o1.y = (oacc[nt][3] + scratch[(iw + g + 8) * AST + col + 1]) * inv1;
            *(float2*)(ctx + ((size_t)b * NN + gi0) * CC + h * DD + col) = o0;
            *(float2*)(ctx + ((size_t)b * NN + gi1) * CC + h * DD + col) = o1;
        }
    }
}

// ---------------- launch ----------------
extern "C" void kernel_launch(void* const* d_in, const int* in_sizes, int n_in,
                              void* d_out, int out_size)
{
    (void)in_sizes; (void)n_in; (void)out_size;
    const float* x     = (const float*)d_in[0];
    const float* Wqkv  = (const float*)d_in[1];
    const float* Wa    = (const float*)d_in[2];
    const float* ba    = (const float*)d_in[3];
    const float* Wproj = (const float*)d_in[4];
    const float* bproj = (const float*)d_in[5];
    float* out = (float*)d_out;

    void *p_qkv, *p_q, *p_k, *p_loga, *p_c, *p_ctx;
    cudaGetSymbolAddress(&p_qkv, g_qkv);
    cudaGetSymbolAddress(&p_q, g_q);
    cudaGetSymbolAddress(&p_k, g_k);
    cudaGetSymbolAddress(&p_loga, g_loga);
    cudaGetSymbolAddress(&p_c, g_c);
    cudaGetSymbolAddress(&p_ctx, g_ctx);

    float* qkv  = (float*)p_qkv;
    float* q    = (float*)p_q;
    float* k    = (float*)p_k;
    float* loga = (float*)p_loga;
    float* cex  = (float*)p_c;
    float* ctx  = (float*)p_ctx;

    gemm_tf32<<<dim3(3 * CC / GBN, BB * NN / GBM), 256>>>(x, Wqkv, nullptr, qkv,
                                                          BB * NN, 3 * CC, CC);
    prep_kernel<<<BB * NN, 384>>>(x, Wa, ba, qkv, q, k, loga);
    scan_kernel<<<BB * HH, NN>>>(loga, cex);
    attn_tf32<<<dim3(BB * HH, NN / 64), 256>>>(q, k, qkv, cex, ctx);
    gemm_tf32<<<dim3(CC / GBN, BB * NN / GBM), 256>>>(ctx, Wproj, bproj, out,
                                                      BB * NN, CC, CC);
}